// round 2
// baseline (speedup 1.0000x reference)
#include <cuda_runtime.h>
#include <math.h>

#define N_MAX 32768
#define F_MAX 256
#define E_MAX 1048576

// ---------------- scratch (device globals: no allocation allowed) ----------------
__device__ float g_bufH[N_MAX * F_MAX];     // GEMM output h = A*W
__device__ float g_bufG[N_MAX * F_MAX];     // aggregation output
__device__ float g_dinv[N_MAX];             // deg^-1/2 (incl. self-loop)
__device__ int   g_cnt[N_MAX];              // in-degree (excl. self-loop)
__device__ int   g_rowptr[N_MAX + 1];       // CSR row pointers (by dst)
__device__ int   g_fill[N_MAX];             // scatter cursors
__device__ int   g_csr[E_MAX];              // CSR column indices (src)
__device__ float g_sum[F_MAX], g_sumsq[F_MAX];
__device__ float g_scale[F_MAX], g_shift[F_MAX];  // fused BN affine
__device__ int   g_i64;                     // edge_index dtype flag

// ---------------- edge_index dtype detection ----------------
__global__ void k_detect(const int* __restrict__ ei) {
    if (threadIdx.x == 0 && blockIdx.x == 0) {
        int z = 1;
        for (int i = 0; i < 32; i++)
            if (ei[2 * i + 1] != 0) z = 0;
        g_i64 = z;
    }
}

__device__ __forceinline__ void edge_sd(const void* ei, int e, int E, int& s, int& d) {
    if (g_i64) {
        const long long* p = (const long long*)ei;
        s = (int)p[e];
        d = (int)p[(long long)E + e];
    } else {
        const int* p = (const int*)ei;
        s = p[e];
        d = p[E + e];
    }
}

// ---------------- degree / CSR build ----------------
__global__ void k_zero_cnt(int N) {
    int i = blockIdx.x * blockDim.x + threadIdx.x;
    if (i < N) g_cnt[i] = 0;
}

__global__ void k_count(const void* __restrict__ ei, int E) {
    int stride = gridDim.x * blockDim.x;
    for (int e = blockIdx.x * blockDim.x + threadIdx.x; e < E; e += stride) {
        int s, d;
        edge_sd(ei, e, E, s, d);
        atomicAdd(&g_cnt[d], 1);
    }
}

__global__ void k_dinv(int N) {
    int i = blockIdx.x * blockDim.x + threadIdx.x;
    if (i < N) g_dinv[i] = rsqrtf((float)g_cnt[i] + 1.0f);  // +1 self-loop
}

// single-block exclusive scan over g_cnt -> g_rowptr, zeroes g_fill. blockDim=1024.
__global__ void k_scan(int N) {
    __shared__ int wsum[32];
    int tid = threadIdx.x;
    int chunk = (N + 1023) >> 10;
    int t0 = tid * chunk, t1 = min(N, t0 + chunk);
    int s = 0;
    for (int i = t0; i < t1; i++) s += g_cnt[i];
    int lane = tid & 31, wid = tid >> 5;
    int v = s;
#pragma unroll
    for (int o = 1; o < 32; o <<= 1) {
        int u = __shfl_up_sync(0xFFFFFFFFu, v, o);
        if (lane >= o) v += u;
    }
    if (lane == 31) wsum[wid] = v;
    __syncthreads();
    if (wid == 0) {
        int w = wsum[lane];
#pragma unroll
        for (int o = 1; o < 32; o <<= 1) {
            int u = __shfl_up_sync(0xFFFFFFFFu, w, o);
            if (lane >= o) w += u;
        }
        wsum[lane] = w;
    }
    __syncthreads();
    int excl = v - s + (wid > 0 ? wsum[wid - 1] : 0);
    int run = excl;
    for (int i = t0; i < t1; i++) {
        g_rowptr[i] = run;
        run += g_cnt[i];
        g_fill[i] = 0;
    }
    if (t0 < N && t1 == N) g_rowptr[N] = run;
}

__global__ void k_scatter(const void* __restrict__ ei, int E) {
    int stride = gridDim.x * blockDim.x;
    for (int e = blockIdx.x * blockDim.x + threadIdx.x; e < E; e += stride) {
        int s, d;
        edge_sd(ei, e, E, s, d);
        int pos = g_rowptr[d] + atomicAdd(&g_fill[d], 1);
        g_csr[pos] = s;
    }
}

// ---------------- fp32 tiled GEMM with fused ReLU+BN-affine on A-load ----------
// C[N,M] = T(A)[N,K] * B[K,M];  T(a)=fmaf(max(a,0),scale[k],shift[k]) if transform
__global__ void k_gemm(const float* __restrict__ A, const float* __restrict__ B,
                       float* __restrict__ C, int N, int K, int M, int transform) {
    __shared__ __align__(16) float As[16][68];
    __shared__ __align__(16) float Bs[16][68];
    int tid = threadIdx.x;        // 256 threads
    int tx = tid & 15, ty = tid >> 4;
    int row0 = blockIdx.y * 64, col0 = blockIdx.x * 64;
    float acc[4][4] = {};

    for (int k0 = 0; k0 < K; k0 += 16) {
        {
            int r  = tid >> 2;
            int c4 = (tid & 3) * 4;
            int gr = row0 + r;
#pragma unroll
            for (int i = 0; i < 4; i++) {
                int gk = k0 + c4 + i;
                float v = 0.0f;
                if (gr < N && gk < K) {
                    v = A[(size_t)gr * K + gk];
                    if (transform) v = fmaf(fmaxf(v, 0.0f), g_scale[gk], g_shift[gk]);
                }
                As[c4 + i][r] = v;
            }
        }
        {
            int lin = tid * 4;
            int r = lin >> 6;
            int c = lin & 63;
            int gk = k0 + r;
#pragma unroll
            for (int i = 0; i < 4; i++) {
                int gc = col0 + c + i;
                Bs[r][c + i] = (gk < K && gc < M) ? B[(size_t)gk * M + gc] : 0.0f;
            }
        }
        __syncthreads();
#pragma unroll
        for (int kk = 0; kk < 16; kk++) {
            float4 a4 = *(const float4*)&As[kk][ty * 4];
            float4 b4 = *(const float4*)&Bs[kk][tx * 4];
            float a[4] = {a4.x, a4.y, a4.z, a4.w};
            float bb[4] = {b4.x, b4.y, b4.z, b4.w};
#pragma unroll
            for (int i = 0; i < 4; i++)
#pragma unroll
                for (int j = 0; j < 4; j++)
                    acc[i][j] = fmaf(a[i], bb[j], acc[i][j]);
        }
        __syncthreads();
    }
#pragma unroll
    for (int i = 0; i < 4; i++) {
        int gr = row0 + ty * 4 + i;
        if (gr >= N) continue;
#pragma unroll
        for (int j = 0; j < 4; j++) {
            int gc = col0 + tx * 4 + j;
            if (gc < M) C[(size_t)gr * M + gc] = acc[i][j];
        }
    }
}

// ---------------- CSR row-gather aggregation (atomic-free) -------------------
// agg[d] = bias + h[d]*dinv[d]^2 + dinv[d] * sum_{s in N(d)} h[s]*dinv[s]
__global__ void k_gather(const float* __restrict__ h, const float* __restrict__ bias,
                         float* __restrict__ agg, int N, int F) {
    int warp = (blockIdx.x * blockDim.x + threadIdx.x) >> 5;
    int lane = threadIdx.x & 31;
    if (warp >= N) return;
    int d = warp;
    int beg = g_rowptr[d], end = g_rowptr[d + 1];
    float dd = g_dinv[d];
    int nch = (F + 31) >> 5;
    float acc[8];
#pragma unroll
    for (int c = 0; c < 8; c++) acc[c] = 0.0f;
    for (int e = beg; e < end; e++) {
        int s = g_csr[e];
        float w = g_dinv[s];
        const float* hr = h + (size_t)s * F;
#pragma unroll 8
        for (int c = 0; c < nch; c++) {
            int f = (c << 5) + lane;
            if (f < F) acc[c] += hr[f] * w;
        }
    }
    const float* hd = h + (size_t)d * F;
    float* ar = agg + (size_t)d * F;
    float sdd = dd * dd;
#pragma unroll 8
    for (int c = 0; c < nch; c++) {
        int f = (c << 5) + lane;
        if (f < F) ar[f] = bias[f] + hd[f] * sdd + acc[c] * dd;
    }
}

// ---------------- BatchNorm(ReLU(x)) stats, row-major coalesced ----------------
__global__ void k_zero_stats() {
    int f = threadIdx.x;
    g_sum[f] = 0.0f;
    g_sumsq[f] = 0.0f;
}

__global__ void k_stats(const float* __restrict__ x, int N, int F) {
    int warp = (blockIdx.x * blockDim.x + threadIdx.x) >> 5;
    int lane = threadIdx.x & 31;
    int nwarp = (gridDim.x * blockDim.x) >> 5;
    int nch = (F + 31) >> 5;
    float s[8], q[8];
#pragma unroll
    for (int c = 0; c < 8; c++) { s[c] = 0.0f; q[c] = 0.0f; }
    for (int r = warp; r < N; r += nwarp) {
        const float* xr = x + (size_t)r * F;
#pragma unroll 8
        for (int c = 0; c < nch; c++) {
            int f = (c << 5) + lane;
            if (f < F) {
                float v = fmaxf(xr[f], 0.0f);
                s[c] += v;
                q[c] += v * v;
            }
        }
    }
#pragma unroll 8
    for (int c = 0; c < nch; c++) {
        int f = (c << 5) + lane;
        if (f < F) {
            atomicAdd(&g_sum[f], s[c]);
            atomicAdd(&g_sumsq[f], q[c]);
        }
    }
}

__global__ void k_fin(int N, int F, const float* __restrict__ g,
                      const float* __restrict__ be) {
    int f = threadIdx.x;
    if (f >= F) return;
    float mu = g_sum[f] / (float)N;
    float var = g_sumsq[f] / (float)N - mu * mu;
    float istd = rsqrtf(fmaxf(var, 0.0f) + 1e-5f);
    float sc = istd * g[f];
    g_scale[f] = sc;
    g_shift[f] = be[f] - mu * sc;
}

// ---------------- final log_softmax (one warp per row; F <= 32) ----------------
__global__ void k_logsoftmax(const float* __restrict__ x, float* __restrict__ out,
                             int N, int F) {
    int warp = (blockIdx.x * blockDim.x + threadIdx.x) >> 5;
    int lane = threadIdx.x & 31;
    if (warp >= N) return;
    float v = (lane < F) ? x[(size_t)warp * F + lane] : -1e30f;
    float m = v;
#pragma unroll
    for (int o = 16; o; o >>= 1) m = fmaxf(m, __shfl_xor_sync(0xFFFFFFFFu, m, o));
    float e = (lane < F) ? expf(v - m) : 0.0f;
    float s = e;
#pragma unroll
    for (int o = 16; o; o >>= 1) s += __shfl_xor_sync(0xFFFFFFFFu, s, o);
    float lse = m + logf(s);
    if (lane < F) out[(size_t)warp * F + lane] = v - lse;
}

// ---------------- orchestration ----------------
extern "C" void kernel_launch(void* const* d_in, const int* in_sizes, int n_in,
                              void* d_out, int out_size) {
    const float* x = (const float*)d_in[0];
    const void* ei = d_in[1];
    const float *W[5], *b[5], *gam[4], *bet[4];
    for (int i = 0; i < 5; i++) {
        W[i] = (const float*)d_in[2 + 2 * i];
        b[i] = (const float*)d_in[3 + 2 * i];
    }
    for (int i = 0; i < 4; i++) {
        gam[i] = (const float*)d_in[12 + 2 * i];
        bet[i] = (const float*)d_in[13 + 2 * i];
    }
    int dims[6];
    for (int i = 0; i < 5; i++) dims[i + 1] = in_sizes[3 + 2 * i];
    dims[0] = in_sizes[2] / dims[1];
    int N = in_sizes[0] / dims[0];
    int E = in_sizes[1] / 2;

    float *bufH, *bufG;
    cudaGetSymbolAddress((void**)&bufH, g_bufH);
    cudaGetSymbolAddress((void**)&bufG, g_bufG);

    // preamble: dtype detect, degrees, dinv, CSR build
    k_detect<<<1, 32>>>((const int*)ei);
    k_zero_cnt<<<(N + 255) / 256, 256>>>(N);
    k_count<<<256, 256>>>(ei, E);
    k_dinv<<<(N + 255) / 256, 256>>>(N);
    k_scan<<<1, 1024>>>(N);
    k_scatter<<<256, 256>>>(ei, E);

    const float* in = x;
    int transform = 0;
    for (int l = 0; l < 5; l++) {
        int K = dims[l], M = dims[l + 1];
        dim3 grid((M + 63) / 64, (N + 63) / 64);
        k_gemm<<<grid, 256>>>(in, W[l], bufH, N, K, M, transform);

        int gblocks = (N * 32 + 255) / 256;
        k_gather<<<gblocks, 256>>>(bufH, b[l], bufG, N, M);

        if (l < 4) {
            k_zero_stats<<<1, F_MAX>>>();
            k_stats<<<128, 256>>>(bufG, N, M);
            k_fin<<<1, 256>>>(N, M, gam[l], bet[l]);
            in = bufG;
            transform = 1;
        } else {
            k_logsoftmax<<<gblocks, 256>>>(bufG, (float*)d_out, N, M);
        }
    }
}

// round 4
// speedup vs baseline: 1.4077x; 1.4077x over previous
#include <cuda_runtime.h>
#include <math.h>

#define N_MAX 16384
#define F_MAX 256

// ---------------- scratch (device globals: no allocation allowed) ----------------
__device__ __align__(16) float g_bufH[N_MAX * F_MAX];   // h = A*W (padded stride)
__device__ __align__(16) float g_bufG0[N_MAX * F_MAX];  // agg ping
__device__ __align__(16) float g_bufG1[N_MAX * F_MAX];  // agg pong
__device__ float g_dinv[N_MAX];                         // deg^-1/2 (incl self-loop)
__device__ float g_sum[F_MAX], g_sumsq[F_MAX];
__device__ float g_scale[F_MAX], g_shift[F_MAX];        // fused ReLU+BN affine
__device__ int   g_i64;                                 // edge_index dtype flag

// ---------------- edge_index dtype detection ----------------
__global__ void k_detect(const int* __restrict__ ei) {
    if (threadIdx.x == 0 && blockIdx.x == 0) {
        int z = 1;
        for (int i = 0; i < 32; i++)
            if (ei[2 * i + 1] != 0) z = 0;
        g_i64 = z;
    }
}

__device__ __forceinline__ void edge_sd(const void* ei, int e, int E, int& s, int& d) {
    if (g_i64) {
        const long long* p = (const long long*)ei;
        s = (int)p[e];
        d = (int)p[(long long)E + e];
    } else {
        const int* p = (const int*)ei;
        s = p[e];
        d = p[E + e];
    }
}

// ---------------- degree / normalization ----------------
__global__ void k_deg_init(int N) {
    int i = blockIdx.x * blockDim.x + threadIdx.x;
    if (i < N) g_dinv[i] = 1.0f;   // self-loop
}

__global__ void k_deg(const void* __restrict__ ei, int E) {
    int stride = gridDim.x * blockDim.x;
    for (int e = blockIdx.x * blockDim.x + threadIdx.x; e < E; e += stride) {
        int s, d;
        edge_sd(ei, e, E, s, d);
        atomicAdd(&g_dinv[d], 1.0f);
    }
}

__global__ void k_dinv(int N) {
    int i = blockIdx.x * blockDim.x + threadIdx.x;
    if (i < N) g_dinv[i] = rsqrtf(g_dinv[i]);
}

// ---------------- fp32 tiled GEMM, fused input transform + fused agg-init ------
// h = T(A) * B ;  T(a) = fmaf(max(a,0), scale[k], shift[k]) when transform
// writes h to H (stride Mp) and  bias + h*dinv[row]^2  to G (stride Mp).
// A and G are DISTINCT buffers (ping-pong) -> no aliasing.
__global__ void k_gemm(const float* __restrict__ A, const float* __restrict__ B,
                       float* __restrict__ H, float* __restrict__ G,
                       const float* __restrict__ bias,
                       int N, int K, int M, int Kp, int Mp, int transform) {
    __shared__ __align__(16) float As[16][68];
    __shared__ __align__(16) float Bs[16][68];
    int tid = threadIdx.x;        // 256 threads
    int tx = tid & 15, ty = tid >> 4;
    int row0 = blockIdx.y * 64, col0 = blockIdx.x * 64;
    float acc[4][4] = {};

    for (int k0 = 0; k0 < K; k0 += 16) {
        {
            int r  = tid >> 2;
            int c4 = (tid & 3) * 4;
            int gr = row0 + r;
#pragma unroll
            for (int i = 0; i < 4; i++) {
                int gk = k0 + c4 + i;
                float v = 0.0f;
                if (gr < N && gk < K) {
                    v = A[(size_t)gr * Kp + gk];
                    if (transform) v = fmaf(fmaxf(v, 0.0f), g_scale[gk], g_shift[gk]);
                }
                As[c4 + i][r] = v;
            }
        }
        {
            int lin = tid * 4;
            int r = lin >> 6;
            int c = lin & 63;
            int gk = k0 + r;
#pragma unroll
            for (int i = 0; i < 4; i++) {
                int gc = col0 + c + i;
                Bs[r][c + i] = (gk < K && gc < M) ? B[(size_t)gk * M + gc] : 0.0f;
            }
        }
        __syncthreads();
#pragma unroll
        for (int kk = 0; kk < 16; kk++) {
            float4 a4 = *(const float4*)&As[kk][ty * 4];
            float4 b4 = *(const float4*)&Bs[kk][tx * 4];
            float a[4] = {a4.x, a4.y, a4.z, a4.w};
            float bb[4] = {b4.x, b4.y, b4.z, b4.w};
#pragma unroll
            for (int i = 0; i < 4; i++)
#pragma unroll
                for (int j = 0; j < 4; j++)
                    acc[i][j] = fmaf(a[i], bb[j], acc[i][j]);
        }
        __syncthreads();
    }
#pragma unroll
    for (int i = 0; i < 4; i++) {
        int gr = row0 + ty * 4 + i;
        if (gr >= N) continue;
        float dd = g_dinv[gr];
        float sdd = dd * dd;
#pragma unroll
        for (int j = 0; j < 4; j++) {
            int gc = col0 + tx * 4 + j;
            if (gc < Mp) {
                float hv = (gc < M) ? acc[i][j] : 0.0f;
                float bv = (gc < M) ? bias[gc] : 0.0f;
                H[(size_t)gr * Mp + gc] = hv;
                G[(size_t)gr * Mp + gc] = bv + hv * sdd;
            }
        }
    }
}

// ---------------- vectorized global reduction -------------------------------
__device__ __forceinline__ void red4(float4* p, float x, float y, float z, float w) {
    asm volatile("red.global.add.v4.f32 [%0], {%1,%2,%3,%4};"
                 :: "l"(p), "f"(x), "f"(y), "f"(z), "f"(w) : "memory");
}

// ---------------- edge aggregation: G[dst] += h[src] * dinv[s]*dinv[d] -------
__global__ void k_edge(const void* __restrict__ ei, int E, int nch4,
                       const float* __restrict__ h, float* __restrict__ agg, int Mp) {
    int lane = threadIdx.x & 31;
    int gwarp = (blockIdx.x * blockDim.x + threadIdx.x) >> 5;
    int nwarp = (gridDim.x * blockDim.x) >> 5;

    if (nch4 > 16) {
        // one edge per warp, lanes stride the float4 chunks
        for (int e = gwarp; e < E; e += nwarp) {
            int s, d;
            edge_sd(ei, e, E, s, d);
            float nrm = g_dinv[s] * g_dinv[d];
            const float4* hr = (const float4*)(h + (size_t)s * Mp);
            float4* ar = (float4*)(agg + (size_t)d * Mp);
            for (int c = lane; c < nch4; c += 32) {
                float4 v = hr[c];
                red4(&ar[c], v.x * nrm, v.y * nrm, v.z * nrm, v.w * nrm);
            }
        }
    } else {
        // multiple edges per warp
        int epw = 32 / nch4;
        int sub = lane / nch4;
        int c = lane - sub * nch4;
        bool act = sub < epw;
        for (int e0 = gwarp * epw; e0 < E; e0 += nwarp * epw) {
            int e = e0 + sub;
            if (act && e < E) {
                int s, d;
                edge_sd(ei, e, E, s, d);
                float nrm = g_dinv[s] * g_dinv[d];
                float4 v = ((const float4*)(h + (size_t)s * Mp))[c];
                float4* ar = (float4*)(agg + (size_t)d * Mp);
                red4(&ar[c], v.x * nrm, v.y * nrm, v.z * nrm, v.w * nrm);
            }
        }
    }
}

// ---------------- BatchNorm(ReLU(x)) stats, row-major coalesced ----------------
__global__ void k_zero_stats() {
    int f = threadIdx.x;
    g_sum[f] = 0.0f;
    g_sumsq[f] = 0.0f;
}

__global__ void k_stats(const float* __restrict__ x, int N, int F, int Mp) {
    int warp = (blockIdx.x * blockDim.x + threadIdx.x) >> 5;
    int lane = threadIdx.x & 31;
    int nwarp = (gridDim.x * blockDim.x) >> 5;
    int nch = (F + 31) >> 5;
    float s[8], q[8];
#pragma unroll
    for (int c = 0; c < 8; c++) { s[c] = 0.0f; q[c] = 0.0f; }
    for (int r = warp; r < N; r += nwarp) {
        const float* xr = x + (size_t)r * Mp;
#pragma unroll 8
        for (int c = 0; c < nch; c++) {
            int f = (c << 5) + lane;
            if (f < F) {
                float v = fmaxf(xr[f], 0.0f);
                s[c] += v;
                q[c] += v * v;
            }
        }
    }
#pragma unroll 8
    for (int c = 0; c < nch; c++) {
        int f = (c << 5) + lane;
        if (f < F) {
            atomicAdd(&g_sum[f], s[c]);
            atomicAdd(&g_sumsq[f], q[c]);
        }
    }
}

__global__ void k_fin(int N, int F, const float* __restrict__ g,
                      const float* __restrict__ be) {
    int f = threadIdx.x;
    if (f >= F) return;
    float mu = g_sum[f] / (float)N;
    float var = g_sumsq[f] / (float)N - mu * mu;
    float istd = rsqrtf(fmaxf(var, 0.0f) + 1e-5f);
    float sc = istd * g[f];
    g_scale[f] = sc;
    g_shift[f] = be[f] - mu * sc;
}

// ---------------- final log_softmax (one warp per row; F <= 32) ----------------
__global__ void k_logsoftmax(const float* __restrict__ x, float* __restrict__ out,
                             int N, int F, int Mp) {
    int warp = (blockIdx.x * blockDim.x + threadIdx.x) >> 5;
    int lane = threadIdx.x & 31;
    if (warp >= N) return;
    float v = (lane < F) ? x[(size_t)warp * Mp + lane] : -1e30f;
    float m = v;
#pragma unroll
    for (int o = 16; o; o >>= 1) m = fmaxf(m, __shfl_xor_sync(0xFFFFFFFFu, m, o));
    float e = (lane < F) ? expf(v - m) : 0.0f;
    float s = e;
#pragma unroll
    for (int o = 16; o; o >>= 1) s += __shfl_xor_sync(0xFFFFFFFFu, s, o);
    float lse = m + logf(s);
    if (lane < F) out[(size_t)warp * F + lane] = v - lse;
}

// ---------------- orchestration ----------------
extern "C" void kernel_launch(void* const* d_in, const int* in_sizes, int n_in,
                              void* d_out, int out_size) {
    const float* x = (const float*)d_in[0];
    const void* ei = d_in[1];
    const float *W[5], *b[5], *gam[4], *bet[4];
    for (int i = 0; i < 5; i++) {
        W[i] = (const float*)d_in[2 + 2 * i];
        b[i] = (const float*)d_in[3 + 2 * i];
    }
    for (int i = 0; i < 4; i++) {
        gam[i] = (const float*)d_in[12 + 2 * i];
        bet[i] = (const float*)d_in[13 + 2 * i];
    }
    int dims[6];
    for (int i = 0; i < 5; i++) dims[i + 1] = in_sizes[3 + 2 * i];
    dims[0] = in_sizes[2] / dims[1];
    int N = in_sizes[0] / dims[0];
    int E = in_sizes[1] / 2;

    float *bufH, *bufG[2];
    cudaGetSymbolAddress((void**)&bufH, g_bufH);
    cudaGetSymbolAddress((void**)&bufG[0], g_bufG0);
    cudaGetSymbolAddress((void**)&bufG[1], g_bufG1);

    // preamble: dtype detect, degrees, dinv
    k_detect<<<1, 32>>>((const int*)ei);
    k_deg_init<<<(N + 255) / 256, 256>>>(N);
    k_deg<<<512, 256>>>(ei, E);
    k_dinv<<<(N + 255) / 256, 256>>>(N);

    const float* in = x;
    int Kp = dims[0];
    int transform = 0;
    for (int l = 0; l < 5; l++) {
        int K = dims[l], M = dims[l + 1];
        int Mp = (M + 3) & ~3;
        float* G = bufG[l & 1];   // ping-pong: never the buffer 'in' points to
        dim3 grid((Mp + 63) / 64, (N + 63) / 64);
        k_gemm<<<grid, 256>>>(in, W[l], bufH, G, b[l], N, K, M, Kp, Mp, transform);

        int nch4 = Mp >> 2;
        int epw = (nch4 > 16) ? 1 : (32 / nch4);
        long long warps_needed = ((long long)E + epw - 1) / epw;
        long long blk = (warps_needed * 32 + 255) / 256;
        int blocks = (int)(blk < 4096 ? blk : 4096);
        k_edge<<<blocks, 256>>>(ei, E, nch4, bufH, G, Mp);

        if (l < 4) {
            k_zero_stats<<<1, F_MAX>>>();
            k_stats<<<128, 256>>>(G, N, M, Mp);
            k_fin<<<1, 256>>>(N, M, gam[l], bet[l]);
            in = G;
            Kp = Mp;
            transform = 1;
        } else {
            int blocks2 = (N * 32 + 255) / 256;
            k_logsoftmax<<<blocks2, 256>>>(G, (float*)d_out, N, M, Mp);
        }
    }
}

// round 5
// speedup vs baseline: 1.4481x; 1.0287x over previous
#include <cuda_runtime.h>
#include <math.h>

#define N_MAX 16384
#define F_MAX 256
#define E_MAX 524288

// ---------------- scratch (device globals: no allocation allowed) ----------------
__device__ __align__(16) float g_bufH[N_MAX * F_MAX];   // h = A*W (padded stride)
__device__ __align__(16) float g_bufG0[N_MAX * F_MAX];  // agg ping
__device__ __align__(16) float g_bufG1[N_MAX * F_MAX];  // agg pong
__device__ float g_dinv[N_MAX];                         // deg^-1/2 (incl self-loop)
__device__ int   g_cin[N_MAX];                          // in-degree (for dinv)
__device__ int   g_cout[N_MAX];                         // out-degree (for CSR)
__device__ int   g_rowptr[N_MAX + 1];                   // CSR by src
__device__ int   g_fill[N_MAX];
__device__ int   g_csr[E_MAX];                          // dst list per src
__device__ float g_sum[F_MAX], g_sumsq[F_MAX];
__device__ float g_scale[F_MAX], g_shift[F_MAX];        // fused ReLU+BN affine
__device__ unsigned g_ticket;
__device__ int   g_i64;

// ---------------- preamble: dtype detect + zero counters ----------------
__global__ void k_init(const int* __restrict__ ei, int N) {
    int i = blockIdx.x * blockDim.x + threadIdx.x;
    if (i < N) { g_cin[i] = 0; g_cout[i] = 0; }
    if (i == 0) {
        int z = 1;
        for (int t = 0; t < 32; t++)
            if (ei[2 * t + 1] != 0) z = 0;
        g_i64 = z;
        g_ticket = 0;
    }
}

__device__ __forceinline__ void edge_sd(const void* ei, int e, int E, int& s, int& d) {
    if (g_i64) {
        const long long* p = (const long long*)ei;
        s = (int)p[e];
        d = (int)p[(long long)E + e];
    } else {
        const int* p = (const int*)ei;
        s = p[e];
        d = p[E + e];
    }
}

__global__ void k_count(const void* __restrict__ ei, int E) {
    int stride = gridDim.x * blockDim.x;
    for (int e = blockIdx.x * blockDim.x + threadIdx.x; e < E; e += stride) {
        int s, d;
        edge_sd(ei, e, E, s, d);
        atomicAdd(&g_cin[d], 1);
        atomicAdd(&g_cout[s], 1);
    }
}

// single block: dinv, exclusive scan of cout -> rowptr, zero fill + stats
__global__ void k_scan(int N) {
    __shared__ int wsum[32];
    int tid = threadIdx.x;             // 1024
    int chunk = (N + 1023) >> 10;
    int t0 = tid * chunk, t1 = min(N, t0 + chunk);
    int s = 0;
    for (int i = t0; i < t1; i++) {
        g_dinv[i] = rsqrtf((float)g_cin[i] + 1.0f);
        s += g_cout[i];
    }
    int lane = tid & 31, wid = tid >> 5;
    int v = s;
#pragma unroll
    for (int o = 1; o < 32; o <<= 1) {
        int u = __shfl_up_sync(0xFFFFFFFFu, v, o);
        if (lane >= o) v += u;
    }
    if (lane == 31) wsum[wid] = v;
    __syncthreads();
    if (wid == 0) {
        int w = wsum[lane];
#pragma unroll
        for (int o = 1; o < 32; o <<= 1) {
            int u = __shfl_up_sync(0xFFFFFFFFu, w, o);
            if (lane >= o) w += u;
        }
        wsum[lane] = w;
    }
    __syncthreads();
    int run = v - s + (wid > 0 ? wsum[wid - 1] : 0);
    for (int i = t0; i < t1; i++) {
        g_rowptr[i] = run;
        run += g_cout[i];
        g_fill[i] = 0;
    }
    if (t0 < N && t1 == N) g_rowptr[N] = run;
    if (tid < F_MAX) { g_sum[tid] = 0.0f; g_sumsq[tid] = 0.0f; }
}

__global__ void k_scatter(const void* __restrict__ ei, int E) {
    int stride = gridDim.x * blockDim.x;
    for (int e = blockIdx.x * blockDim.x + threadIdx.x; e < E; e += stride) {
        int s, d;
        edge_sd(ei, e, E, s, d);
        int pos = g_rowptr[s] + atomicAdd(&g_fill[s], 1);
        g_csr[pos] = d;
    }
}

// ---------------- fp32 tiled GEMM, fused input transform + fused agg-init ------
__global__ void k_gemm(const float* __restrict__ A, const float* __restrict__ B,
                       float* __restrict__ H, float* __restrict__ G,
                       const float* __restrict__ bias,
                       int N, int K, int M, int Kp, int Mp, int transform) {
    __shared__ __align__(16) float As[16][68];
    __shared__ __align__(16) float Bs[16][68];
    int tid = threadIdx.x;        // 256
    int tx = tid & 15, ty = tid >> 4;
    int row0 = blockIdx.y * 64, col0 = blockIdx.x * 64;
    float acc[4][4] = {};

    for (int k0 = 0; k0 < K; k0 += 16) {
        {
            int r  = tid >> 2;
            int c4 = (tid & 3) * 4;
            int gr = row0 + r;
#pragma unroll
            for (int i = 0; i < 4; i++) {
                int gk = k0 + c4 + i;
                float v = 0.0f;
                if (gr < N && gk < K) {
                    v = A[(size_t)gr * Kp + gk];
                    if (transform) v = fmaf(fmaxf(v, 0.0f), g_scale[gk], g_shift[gk]);
                }
                As[c4 + i][r] = v;
            }
        }
        {
            int lin = tid * 4;
            int r = lin >> 6;
            int c = lin & 63;
            int gk = k0 + r;
#pragma unroll
            for (int i = 0; i < 4; i++) {
                int gc = col0 + c + i;
                Bs[r][c + i] = (gk < K && gc < M) ? B[(size_t)gk * M + gc] : 0.0f;
            }
        }
        __syncthreads();
#pragma unroll
        for (int kk = 0; kk < 16; kk++) {
            float4 a4 = *(const float4*)&As[kk][ty * 4];
            float4 b4 = *(const float4*)&Bs[kk][tx * 4];
            float a[4] = {a4.x, a4.y, a4.z, a4.w};
            float bb[4] = {b4.x, b4.y, b4.z, b4.w};
#pragma unroll
            for (int i = 0; i < 4; i++)
#pragma unroll
                for (int j = 0; j < 4; j++)
                    acc[i][j] = fmaf(a[i], bb[j], acc[i][j]);
        }
        __syncthreads();
    }
#pragma unroll
    for (int i = 0; i < 4; i++) {
        int gr = row0 + ty * 4 + i;
        if (gr >= N) continue;
        float dd = g_dinv[gr];
        float sdd = dd * dd;
#pragma unroll
        for (int j = 0; j < 4; j++) {
            int gc = col0 + tx * 4 + j;
            if (gc < Mp) {
                float hv = (gc < M) ? acc[i][j] : 0.0f;
                float bv = (gc < M) ? bias[gc] : 0.0f;
                H[(size_t)gr * Mp + gc] = hv;
                G[(size_t)gr * Mp + gc] = bv + hv * sdd;
            }
        }
    }
}

// ---------------- vectorized global reduction -------------------------------
__device__ __forceinline__ void red4(float4* p, float x, float y, float z, float w) {
    asm volatile("red.global.add.v4.f32 [%0], {%1,%2,%3,%4};"
                 :: "l"(p), "f"(x), "f"(y), "f"(z), "f"(w) : "memory");
}

// ---------------- CSR push: for each src, read row once, RED to neighbors ----
// G[d] += (h[s] * dinv[s]) * dinv[d]   for all d in adj(s)
__global__ void k_push(const float* __restrict__ h, float* __restrict__ agg,
                       int N, int nch4, int Mp) {
    int lane = threadIdx.x & 31;
    int gwarp = (blockIdx.x * blockDim.x + threadIdx.x) >> 5;
    int nwarp = (gridDim.x * blockDim.x) >> 5;

    if (nch4 >= 32) {
        // lane handles chunks lane, lane+32
        for (int s = gwarp; s < N; s += nwarp) {
            int beg = g_rowptr[s], end = g_rowptr[s + 1];
            if (beg == end) continue;
            float ds = g_dinv[s];
            const float4* hr = (const float4*)(h + (size_t)s * Mp);
            int c1 = lane + 32;
            bool has1 = c1 < nch4;
            float4 v0 = hr[lane];
            float4 v1 = has1 ? hr[c1] : make_float4(0, 0, 0, 0);
            v0.x *= ds; v0.y *= ds; v0.z *= ds; v0.w *= ds;
            v1.x *= ds; v1.y *= ds; v1.z *= ds; v1.w *= ds;
            int e = beg;
            for (; e + 1 < end; e += 2) {
                int d0 = g_csr[e], d1 = g_csr[e + 1];
                float w0 = g_dinv[d0], w1 = g_dinv[d1];
                float4* a0 = (float4*)(agg + (size_t)d0 * Mp);
                float4* a1 = (float4*)(agg + (size_t)d1 * Mp);
                red4(&a0[lane], v0.x * w0, v0.y * w0, v0.z * w0, v0.w * w0);
                red4(&a1[lane], v0.x * w1, v0.y * w1, v0.z * w1, v0.w * w1);
                if (has1) {
                    red4(&a0[c1], v1.x * w0, v1.y * w0, v1.z * w0, v1.w * w0);
                    red4(&a1[c1], v1.x * w1, v1.y * w1, v1.z * w1, v1.w * w1);
                }
            }
            if (e < end) {
                int d0 = g_csr[e];
                float w0 = g_dinv[d0];
                float4* a0 = (float4*)(agg + (size_t)d0 * Mp);
                red4(&a0[lane], v0.x * w0, v0.y * w0, v0.z * w0, v0.w * w0);
                if (has1) red4(&a0[c1], v1.x * w0, v1.y * w0, v1.z * w0, v1.w * w0);
            }
        }
    } else {
        // nch4 < 32: epw sub-groups process different edges of the same src
        int epw = 32 / nch4;
        int sub = lane / nch4;
        int c = lane - sub * nch4;
        bool act = sub < epw;
        for (int s = gwarp; s < N; s += nwarp) {
            int beg = g_rowptr[s], end = g_rowptr[s + 1];
            if (beg == end) continue;
            float ds = g_dinv[s];
            float4 v = make_float4(0, 0, 0, 0);
            if (act) {
                v = ((const float4*)(h + (size_t)s * Mp))[c];
                v.x *= ds; v.y *= ds; v.z *= ds; v.w *= ds;
            }
            for (int e = beg + sub; act && e < end; e += epw) {
                int d = g_csr[e];
                float w = g_dinv[d];
                float4* a = (float4*)(agg + (size_t)d * Mp);
                red4(&a[c], v.x * w, v.y * w, v.z * w, v.w * w);
            }
        }
    }
}

// ---------------- fused BN stats + finalize (last-block ticket) --------------
__global__ void k_statsfin(const float* __restrict__ x, int N, int F, int Mp,
                           const float* __restrict__ g, const float* __restrict__ be) {
    int tid = threadIdx.x;
    int warp = (blockIdx.x * blockDim.x + tid) >> 5;
    int lane = tid & 31;
    int nwarp = (gridDim.x * blockDim.x) >> 5;
    int nch = (F + 31) >> 5;
    float s[8], q[8];
#pragma unroll
    for (int c = 0; c < 8; c++) { s[c] = 0.0f; q[c] = 0.0f; }
    for (int r = warp; r < N; r += nwarp) {
        const float* xr = x + (size_t)r * Mp;
#pragma unroll 8
        for (int c = 0; c < nch; c++) {
            int f = (c << 5) + lane;
            if (f < F) {
                float v = fmaxf(xr[f], 0.0f);
                s[c] += v;
                q[c] += v * v;
            }
        }
    }
#pragma unroll 8
    for (int c = 0; c < nch; c++) {
        int f = (c << 5) + lane;
        if (f < F) {
            atomicAdd(&g_sum[f], s[c]);
            atomicAdd(&g_sumsq[f], q[c]);
        }
    }
    __threadfence();
    __syncthreads();
    __shared__ int is_last;
    if (tid == 0) {
        unsigned t = atomicAdd(&g_ticket, 1u);
        is_last = (t == gridDim.x - 1);
    }
    __syncthreads();
    if (is_last) {
        int f = tid;
        if (f < F) {
            float mu = g_sum[f] / (float)N;
            float var = g_sumsq[f] / (float)N - mu * mu;
            float istd = rsqrtf(fmaxf(var, 0.0f) + 1e-5f);
            float sc = istd * g[f];
            g_scale[f] = sc;
            g_shift[f] = be[f] - mu * sc;
        }
        if (f < F_MAX) { g_sum[f] = 0.0f; g_sumsq[f] = 0.0f; }
        if (tid == 0) g_ticket = 0;
    }
}

// ---------------- final log_softmax (one warp per row; F <= 32) ----------------
__global__ void k_logsoftmax(const float* __restrict__ x, float* __restrict__ out,
                             int N, int F, int Mp) {
    int warp = (blockIdx.x * blockDim.x + threadIdx.x) >> 5;
    int lane = threadIdx.x & 31;
    if (warp >= N) return;
    float v = (lane < F) ? x[(size_t)warp * Mp + lane] : -1e30f;
    float m = v;
#pragma unroll
    for (int o = 16; o; o >>= 1) m = fmaxf(m, __shfl_xor_sync(0xFFFFFFFFu, m, o));
    float e = (lane < F) ? expf(v - m) : 0.0f;
    float s = e;
#pragma unroll
    for (int o = 16; o; o >>= 1) s += __shfl_xor_sync(0xFFFFFFFFu, s, o);
    float lse = m + logf(s);
    if (lane < F) out[(size_t)warp * F + lane] = v - lse;
}

// ---------------- orchestration ----------------
extern "C" void kernel_launch(void* const* d_in, const int* in_sizes, int n_in,
                              void* d_out, int out_size) {
    const float* x = (const float*)d_in[0];
    const void* ei = d_in[1];
    const float *W[5], *b[5], *gam[4], *bet[4];
    for (int i = 0; i < 5; i++) {
        W[i] = (const float*)d_in[2 + 2 * i];
        b[i] = (const float*)d_in[3 + 2 * i];
    }
    for (int i = 0; i < 4; i++) {
        gam[i] = (const float*)d_in[12 + 2 * i];
        bet[i] = (const float*)d_in[13 + 2 * i];
    }
    int dims[6];
    for (int i = 0; i < 5; i++) dims[i + 1] = in_sizes[3 + 2 * i];
    dims[0] = in_sizes[2] / dims[1];
    int N = in_sizes[0] / dims[0];
    int E = in_sizes[1] / 2;

    float *bufH, *bufG[2];
    cudaGetSymbolAddress((void**)&bufH, g_bufH);
    cudaGetSymbolAddress((void**)&bufG[0], g_bufG0);
    cudaGetSymbolAddress((void**)&bufG[1], g_bufG1);

    // preamble: 4 launches
    k_init<<<(N + 255) / 256, 256>>>((const int*)ei, N);
    k_count<<<256, 256>>>(ei, E);
    k_scan<<<1, 1024>>>(N);
    k_scatter<<<256, 256>>>(ei, E);

    const float* in = x;
    int Kp = dims[0];
    int transform = 0;
    for (int l = 0; l < 5; l++) {
        int K = dims[l], M = dims[l + 1];
        int Mp = (M + 3) & ~3;
        float* G = bufG[l & 1];
        dim3 grid((Mp + 63) / 64, (N + 63) / 64);
        k_gemm<<<grid, 256>>>(in, W[l], bufH, G, b[l], N, K, M, Kp, Mp, transform);

        int nch4 = Mp >> 2;
        int pblocks = (N * 32 + 255) / 256;   // one warp per src
        k_push<<<pblocks, 256>>>(bufH, G, N, nch4, Mp);

        if (l < 4) {
            k_statsfin<<<120, 256>>>(G, N, M, Mp, gam[l], bet[l]);
            in = G;
            Kp = Mp;
            transform = 1;
        } else {
            int blocks2 = (N * 32 + 255) / 256;
            k_logsoftmax<<<blocks2, 256>>>(G, (float*)d_out, N, M, Mp);
        }
    }
}

// round 6
// speedup vs baseline: 1.9610x; 1.3542x over previous
#include <cuda_runtime.h>
#include <math.h>

#define N_MAX 16384
#define F_MAX 256
#define E_MAX 524288

// ---------------- scratch (device globals: no allocation allowed) ----------------
__device__ __align__(16) float g_bufH[N_MAX * F_MAX];   // Hs = h * dinv[row]
__device__ __align__(16) float g_bufG0[N_MAX * F_MAX];  // agg ping
__device__ __align__(16) float g_bufG1[N_MAX * F_MAX];  // agg pong
__device__ float g_dinv[N_MAX];                         // deg^-1/2 (incl self-loop)
__device__ int   g_cin[N_MAX];                          // in-degree
__device__ int   g_rowptr[N_MAX + 1];                   // CSR by dst
__device__ int   g_fill[N_MAX];
__device__ int   g_csr[E_MAX];                          // src list per dst
__device__ float g_sum[F_MAX], g_sumsq[F_MAX];
__device__ float g_scale[F_MAX], g_shift[F_MAX];        // fused ReLU+BN affine
__device__ unsigned g_ticket;
__device__ int   g_i64;

// ---------------- preamble ----------------
__global__ void k_init(const int* __restrict__ ei, int N) {
    int i = blockIdx.x * blockDim.x + threadIdx.x;
    if (i < N) g_cin[i] = 0;
    if (i == 0) {
        int z = 1;
        for (int t = 0; t < 32; t++)
            if (ei[2 * t + 1] != 0) z = 0;
        g_i64 = z;
        g_ticket = 0;
    }
}

__device__ __forceinline__ void edge_sd(const void* ei, int e, int E, int& s, int& d) {
    if (g_i64) {
        const long long* p = (const long long*)ei;
        s = (int)p[e];
        d = (int)p[(long long)E + e];
    } else {
        const int* p = (const int*)ei;
        s = p[e];
        d = p[E + e];
    }
}

__global__ void k_count(const void* __restrict__ ei, int E) {
    int stride = gridDim.x * blockDim.x;
    for (int e = blockIdx.x * blockDim.x + threadIdx.x; e < E; e += stride) {
        int s, d;
        edge_sd(ei, e, E, s, d);
        atomicAdd(&g_cin[d], 1);
    }
}

// single block (1024 thr): dinv, exclusive scan cin -> rowptr, zero fill + stats
__global__ void k_scan(int N) {
    __shared__ int wsum[32];
    int tid = threadIdx.x;
    int chunk = (N + 1023) >> 10;
    int t0 = tid * chunk, t1 = min(N, t0 + chunk);
    int s = 0;
    for (int i = t0; i < t1; i++) {
        int c = g_cin[i];
        g_dinv[i] = rsqrtf((float)c + 1.0f);
        s += c;
    }
    int lane = tid & 31, wid = tid >> 5;
    int v = s;
#pragma unroll
    for (int o = 1; o < 32; o <<= 1) {
        int u = __shfl_up_sync(0xFFFFFFFFu, v, o);
        if (lane >= o) v += u;
    }
    if (lane == 31) wsum[wid] = v;
    __syncthreads();
    if (wid == 0) {
        int w = wsum[lane];
#pragma unroll
        for (int o = 1; o < 32; o <<= 1) {
            int u = __shfl_up_sync(0xFFFFFFFFu, w, o);
            if (lane >= o) w += u;
        }
        wsum[lane] = w;
    }
    __syncthreads();
    int run = v - s + (wid > 0 ? wsum[wid - 1] : 0);
    for (int i = t0; i < t1; i++) {
        g_rowptr[i] = run;
        run += g_cin[i];
        g_fill[i] = 0;
    }
    if (t0 < N && t1 == N) g_rowptr[N] = run;
    if (tid < F_MAX) { g_sum[tid] = 0.0f; g_sumsq[tid] = 0.0f; }
}

__global__ void k_scatter(const void* __restrict__ ei, int E) {
    int stride = gridDim.x * blockDim.x;
    for (int e = blockIdx.x * blockDim.x + threadIdx.x; e < E; e += stride) {
        int s, d;
        edge_sd(ei, e, E, s, d);
        int pos = g_rowptr[d] + atomicAdd(&g_fill[d], 1);
        g_csr[pos] = s;
    }
}

// ---------------- fp32 tiled GEMM, fused input transform, writes Hs = h*dinv ----
__global__ void k_gemm(const float* __restrict__ A, const float* __restrict__ B,
                       float* __restrict__ Hs,
                       int N, int K, int M, int Kp, int Mp, int transform) {
    __shared__ __align__(16) float As[16][68];
    __shared__ __align__(16) float Bs[16][68];
    int tid = threadIdx.x;        // 256
    int tx = tid & 15, ty = tid >> 4;
    int row0 = blockIdx.y * 64, col0 = blockIdx.x * 64;
    float acc[4][4] = {};

    for (int k0 = 0; k0 < K; k0 += 16) {
        {
            int r  = tid >> 2;
            int c4 = (tid & 3) * 4;
            int gr = row0 + r;
#pragma unroll
            for (int i = 0; i < 4; i++) {
                int gk = k0 + c4 + i;
                float v = 0.0f;
                if (gr < N && gk < K) {
                    v = A[(size_t)gr * Kp + gk];
                    if (transform) v = fmaf(fmaxf(v, 0.0f), g_scale[gk], g_shift[gk]);
                }
                As[c4 + i][r] = v;
            }
        }
        {
            int lin = tid * 4;
            int r = lin >> 6;
            int c = lin & 63;
            int gk = k0 + r;
#pragma unroll
            for (int i = 0; i < 4; i++) {
                int gc = col0 + c + i;
                Bs[r][c + i] = (gk < K && gc < M) ? B[(size_t)gk * M + gc] : 0.0f;
            }
        }
        __syncthreads();
#pragma unroll
        for (int kk = 0; kk < 16; kk++) {
            float4 a4 = *(const float4*)&As[kk][ty * 4];
            float4 b4 = *(const float4*)&Bs[kk][tx * 4];
            float a[4] = {a4.x, a4.y, a4.z, a4.w};
            float bb[4] = {b4.x, b4.y, b4.z, b4.w};
#pragma unroll
            for (int i = 0; i < 4; i++)
#pragma unroll
                for (int j = 0; j < 4; j++)
                    acc[i][j] = fmaf(a[i], bb[j], acc[i][j]);
        }
        __syncthreads();
    }
#pragma unroll
    for (int i = 0; i < 4; i++) {
        int gr = row0 + ty * 4 + i;
        if (gr >= N) continue;
        float dd = g_dinv[gr];
#pragma unroll
        for (int j = 0; j < 4; j++) {
            int gc = col0 + tx * 4 + j;
            if (gc < Mp)
                Hs[(size_t)gr * Mp + gc] = (gc < M) ? acc[i][j] * dd : 0.0f;
        }
    }
}

// ---------------- coalesced CSR pull + fused BN stats/finalize ----------------
// out[d] = bias + dinv[d] * (Hs[d] + sum_{s in N(d)} Hs[s])
__global__ void k_pull(const float* __restrict__ Hs, const float* __restrict__ bias,
                       float* __restrict__ G, int N, int M, int Mp,
                       int nch4, int ngroups, int do_stats,
                       const float* __restrict__ gam, const float* __restrict__ bet) {
    __shared__ float sm_s[F_MAX], sm_q[F_MAX];
    int tid = threadIdx.x;
    if (do_stats) {
        for (int f = tid; f < F_MAX; f += blockDim.x) { sm_s[f] = 0.0f; sm_q[f] = 0.0f; }
        __syncthreads();
    }
    int lane = tid & 31;
    int gw = (blockIdx.x * blockDim.x + tid) >> 5;
    int nw = (gridDim.x * blockDim.x) >> 5;
    int grp = gw % ngroups;
    int c = (grp << 5) + lane;
    bool act = c < nch4;
    int f0 = c << 2;
    float4 b4 = make_float4(0, 0, 0, 0);
    if (act) {
        b4.x = (f0 + 0 < M) ? bias[f0 + 0] : 0.0f;
        b4.y = (f0 + 1 < M) ? bias[f0 + 1] : 0.0f;
        b4.z = (f0 + 2 < M) ? bias[f0 + 2] : 0.0f;
        b4.w = (f0 + 3 < M) ? bias[f0 + 3] : 0.0f;
    }
    float4 ls = make_float4(0, 0, 0, 0), lq = make_float4(0, 0, 0, 0);

    for (int d = gw / ngroups; d < N; d += nw / ngroups) {
        if (!act) continue;
        int beg = g_rowptr[d], end = g_rowptr[d + 1];
        // self term
        float4 acc = ((const float4*)(Hs + (size_t)d * Mp))[c];
        int e = beg;
        for (; e + 3 < end; e += 4) {
            int s0 = g_csr[e], s1 = g_csr[e + 1], s2 = g_csr[e + 2], s3 = g_csr[e + 3];
            float4 v0 = ((const float4*)(Hs + (size_t)s0 * Mp))[c];
            float4 v1 = ((const float4*)(Hs + (size_t)s1 * Mp))[c];
            float4 v2 = ((const float4*)(Hs + (size_t)s2 * Mp))[c];
            float4 v3 = ((const float4*)(Hs + (size_t)s3 * Mp))[c];
            acc.x += (v0.x + v1.x) + (v2.x + v3.x);
            acc.y += (v0.y + v1.y) + (v2.y + v3.y);
            acc.z += (v0.z + v1.z) + (v2.z + v3.z);
            acc.w += (v0.w + v1.w) + (v2.w + v3.w);
        }
        for (; e < end; e++) {
            int s0 = g_csr[e];
            float4 v0 = ((const float4*)(Hs + (size_t)s0 * Mp))[c];
            acc.x += v0.x; acc.y += v0.y; acc.z += v0.z; acc.w += v0.w;
        }
        float dd = g_dinv[d];
        float4 o;
        o.x = fmaf(dd, acc.x, b4.x);
        o.y = fmaf(dd, acc.y, b4.y);
        o.z = fmaf(dd, acc.z, b4.z);
        o.w = fmaf(dd, acc.w, b4.w);
        ((float4*)(G + (size_t)d * Mp))[c] = o;
        if (do_stats) {
            float rx = fmaxf(o.x, 0.0f), ry = fmaxf(o.y, 0.0f);
            float rz = fmaxf(o.z, 0.0f), rw = fmaxf(o.w, 0.0f);
            ls.x += rx; ls.y += ry; ls.z += rz; ls.w += rw;
            lq.x += rx * rx; lq.y += ry * ry; lq.z += rz * rz; lq.w += rw * rw;
        }
    }

    if (!do_stats) return;
    if (act) {
        atomicAdd(&sm_s[f0 + 0], ls.x); atomicAdd(&sm_q[f0 + 0], lq.x);
        atomicAdd(&sm_s[f0 + 1], ls.y); atomicAdd(&sm_q[f0 + 1], lq.y);
        atomicAdd(&sm_s[f0 + 2], ls.z); atomicAdd(&sm_q[f0 + 2], lq.z);
        atomicAdd(&sm_s[f0 + 3], ls.w); atomicAdd(&sm_q[f0 + 3], lq.w);
    }
    __syncthreads();
    for (int f = tid; f < M; f += blockDim.x) {
        atomicAdd(&g_sum[f], sm_s[f]);
        atomicAdd(&g_sumsq[f], sm_q[f]);
    }
    __threadfence();
    __syncthreads();
    __shared__ int is_last;
    if (tid == 0) {
        unsigned t = atomicAdd(&g_ticket, 1u);
        is_last = (t == gridDim.x - 1);
    }
    __syncthreads();
    if (is_last) {
        for (int f = tid; f < M; f += blockDim.x) {
            float mu = g_sum[f] / (float)N;
            float var = g_sumsq[f] / (float)N - mu * mu;
            float istd = rsqrtf(fmaxf(var, 0.0f) + 1e-5f);
            float sc = istd * gam[f];
            g_scale[f] = sc;
            g_shift[f] = bet[f] - mu * sc;
            g_sum[f] = 0.0f;
            g_sumsq[f] = 0.0f;
        }
        if (tid == 0) g_ticket = 0;
    }
}

// ---------------- final log_softmax (one warp per row; F <= 32) ----------------
__global__ void k_logsoftmax(const float* __restrict__ x, float* __restrict__ out,
                             int N, int F, int Mp) {
    int warp = (blockIdx.x * blockDim.x + threadIdx.x) >> 5;
    int lane = threadIdx.x & 31;
    if (warp >= N) return;
    float v = (lane < F) ? x[(size_t)warp * Mp + lane] : -1e30f;
    float m = v;
#pragma unroll
    for (int o = 16; o; o >>= 1) m = fmaxf(m, __shfl_xor_sync(0xFFFFFFFFu, m, o));
    float e = (lane < F) ? expf(v - m) : 0.0f;
    float s = e;
#pragma unroll
    for (int o = 16; o; o >>= 1) s += __shfl_xor_sync(0xFFFFFFFFu, s, o);
    float lse = m + logf(s);
    if (lane < F) out[(size_t)warp * F + lane] = v - lse;
}

// ---------------- orchestration ----------------
extern "C" void kernel_launch(void* const* d_in, const int* in_sizes, int n_in,
                              void* d_out, int out_size) {
    const float* x = (const float*)d_in[0];
    const void* ei = d_in[1];
    const float *W[5], *b[5], *gam[4], *bet[4];
    for (int i = 0; i < 5; i++) {
        W[i] = (const float*)d_in[2 + 2 * i];
        b[i] = (const float*)d_in[3 + 2 * i];
    }
    for (int i = 0; i < 4; i++) {
        gam[i] = (const float*)d_in[12 + 2 * i];
        bet[i] = (const float*)d_in[13 + 2 * i];
    }
    int dims[6];
    for (int i = 0; i < 5; i++) dims[i + 1] = in_sizes[3 + 2 * i];
    dims[0] = in_sizes[2] / dims[1];
    int N = in_sizes[0] / dims[0];
    int E = in_sizes[1] / 2;

    float *bufH, *bufG[2];
    cudaGetSymbolAddress((void**)&bufH, g_bufH);
    cudaGetSymbolAddress((void**)&bufG[0], g_bufG0);
    cudaGetSymbolAddress((void**)&bufG[1], g_bufG1);

    // preamble: 4 launches
    k_init<<<(N + 255) / 256, 256>>>((const int*)ei, N);
    k_count<<<256, 256>>>(ei, E);
    k_scan<<<1, 1024>>>(N);
    k_scatter<<<256, 256>>>(ei, E);

    const float* in = x;
    int Kp = dims[0];
    int transform = 0;
    for (int l = 0; l < 5; l++) {
        int K = dims[l], M = dims[l + 1];
        int Mp = (M + 3) & ~3;
        float* G = bufG[l & 1];
        dim3 grid((Mp + 63) / 64, (N + 63) / 64);
        k_gemm<<<grid, 256>>>(in, W[l], bufH, N, K, M, Kp, Mp, transform);

        int nch4 = Mp >> 2;
        int ngroups = (nch4 + 31) >> 5;   // 1 or 2
        int do_stats = (l < 4);
        k_pull<<<1184, 256>>>(bufH, b[l], G, N, M, Mp, nch4, ngroups, do_stats,
                              do_stats ? gam[l] : b[l], do_stats ? bet[l] : b[l]);

        if (l < 4) {
            in = G;
            Kp = Mp;
            transform = 1;
        } else {
            int blocks2 = (N * 32 + 255) / 256;
            k_logsoftmax<<<blocks2, 256>>>(G, (float*)d_out, N, M, Mp);
        }
    }
}

// round 7
// speedup vs baseline: 2.0917x; 1.0667x over previous
#include <cuda_runtime.h>
#include <math.h>

#define N_MAX 16384
#define F_MAX 256
#define E_MAX 524288

// ---------------- scratch (device globals: no allocation allowed) ----------------
__device__ __align__(16) float g_bufH[N_MAX * F_MAX];   // Hs = h * dinv[row]
__device__ __align__(16) float g_bufG0[N_MAX * F_MAX];  // agg ping
__device__ __align__(16) float g_bufG1[N_MAX * F_MAX];  // agg pong
__device__ float g_dinv[N_MAX];
__device__ int   g_cin[N_MAX];
__device__ int   g_rowptr[N_MAX + 1];
__device__ int   g_fill[N_MAX];
__device__ int   g_csr[E_MAX];
__device__ float g_sum[F_MAX], g_sumsq[F_MAX];
__device__ float g_scale[F_MAX], g_shift[F_MAX];
__device__ unsigned g_ticket;
__device__ int   g_i64;

// ---------------- preamble ----------------
__global__ void k_init(const int* __restrict__ ei, int N) {
    int i = blockIdx.x * blockDim.x + threadIdx.x;
    if (i < N) g_cin[i] = 0;
    if (i == 0) {
        int z = 1;
        for (int t = 0; t < 32; t++)
            if (ei[2 * t + 1] != 0) z = 0;
        g_i64 = z;
        g_ticket = 0;
    }
}

__device__ __forceinline__ void edge_sd(const void* ei, int e, int E, int& s, int& d) {
    if (g_i64) {
        const long long* p = (const long long*)ei;
        s = (int)p[e];
        d = (int)p[(long long)E + e];
    } else {
        const int* p = (const int*)ei;
        s = p[e];
        d = p[E + e];
    }
}

__global__ void k_count(const void* __restrict__ ei, int E) {
    int stride = gridDim.x * blockDim.x;
    for (int e = blockIdx.x * blockDim.x + threadIdx.x; e < E; e += stride) {
        int s, d;
        edge_sd(ei, e, E, s, d);
        atomicAdd(&g_cin[d], 1);
    }
}

__global__ void k_scan(int N) {
    __shared__ int wsum[32];
    int tid = threadIdx.x;
    int chunk = (N + 1023) >> 10;
    int t0 = tid * chunk, t1 = min(N, t0 + chunk);
    int s = 0;
    for (int i = t0; i < t1; i++) {
        int c = g_cin[i];
        g_dinv[i] = rsqrtf((float)c + 1.0f);
        s += c;
    }
    int lane = tid & 31, wid = tid >> 5;
    int v = s;
#pragma unroll
    for (int o = 1; o < 32; o <<= 1) {
        int u = __shfl_up_sync(0xFFFFFFFFu, v, o);
        if (lane >= o) v += u;
    }
    if (lane == 31) wsum[wid] = v;
    __syncthreads();
    if (wid == 0) {
        int w = wsum[lane];
#pragma unroll
        for (int o = 1; o < 32; o <<= 1) {
            int u = __shfl_up_sync(0xFFFFFFFFu, w, o);
            if (lane >= o) w += u;
        }
        wsum[lane] = w;
    }
    __syncthreads();
    int run = v - s + (wid > 0 ? wsum[wid - 1] : 0);
    for (int i = t0; i < t1; i++) {
        g_rowptr[i] = run;
        run += g_cin[i];
        g_fill[i] = 0;
    }
    if (t0 < N && t1 == N) g_rowptr[N] = run;
    if (tid < F_MAX) { g_sum[tid] = 0.0f; g_sumsq[tid] = 0.0f; }
}

__global__ void k_scatter(const void* __restrict__ ei, int E) {
    int stride = gridDim.x * blockDim.x;
    for (int e = blockIdx.x * blockDim.x + threadIdx.x; e < E; e += stride) {
        int s, d;
        edge_sd(ei, e, E, s, d);
        int pos = g_rowptr[d] + atomicAdd(&g_fill[d], 1);
        g_csr[pos] = s;
    }
}

// ---------------- GEMM 64x64 tile (4x4 micro), for narrow layers ---------------
__global__ void k_gemm64(const float* __restrict__ A, const float* __restrict__ B,
                         float* __restrict__ Hs,
                         int N, int K, int M, int Kp, int Mp, int transform) {
    __shared__ __align__(16) float As[16][68];
    __shared__ __align__(16) float Bs[16][68];
    int tid = threadIdx.x;
    int tx = tid & 15, ty = tid >> 4;
    int row0 = blockIdx.y * 64, col0 = blockIdx.x * 64;
    float acc[4][4] = {};

    for (int k0 = 0; k0 < K; k0 += 16) {
        {
            int r  = tid >> 2;
            int c4 = (tid & 3) * 4;
            int gr = row0 + r;
#pragma unroll
            for (int i = 0; i < 4; i++) {
                int gk = k0 + c4 + i;
                float v = 0.0f;
                if (gr < N && gk < K) {
                    v = A[(size_t)gr * Kp + gk];
                    if (transform) v = fmaf(fmaxf(v, 0.0f), g_scale[gk], g_shift[gk]);
                }
                As[c4 + i][r] = v;
            }
        }
        {
            int lin = tid * 4;
            int r = lin >> 6;
            int c = lin & 63;
            int gk = k0 + r;
#pragma unroll
            for (int i = 0; i < 4; i++) {
                int gc = col0 + c + i;
                Bs[r][c + i] = (gk < K && gc < M) ? B[(size_t)gk * M + gc] : 0.0f;
            }
        }
        __syncthreads();
#pragma unroll
        for (int kk = 0; kk < 16; kk++) {
            float4 a4 = *(const float4*)&As[kk][ty * 4];
            float4 b4 = *(const float4*)&Bs[kk][tx * 4];
            float a[4] = {a4.x, a4.y, a4.z, a4.w};
            float bb[4] = {b4.x, b4.y, b4.z, b4.w};
#pragma unroll
            for (int i = 0; i < 4; i++)
#pragma unroll
                for (int j = 0; j < 4; j++)
                    acc[i][j] = fmaf(a[i], bb[j], acc[i][j]);
        }
        __syncthreads();
    }
#pragma unroll
    for (int i = 0; i < 4; i++) {
        int gr = row0 + ty * 4 + i;
        if (gr >= N) continue;
        float dd = g_dinv[gr];
#pragma unroll
        for (int j = 0; j < 4; j++) {
            int gc = col0 + tx * 4 + j;
            if (gc < Mp)
                Hs[(size_t)gr * Mp + gc] = (gc < M) ? acc[i][j] * dd : 0.0f;
        }
    }
}

// ---------------- GEMM 128x64 tile (8x4 micro), for wide layers ----------------
__global__ void k_gemm128(const float* __restrict__ A, const float* __restrict__ B,
                          float* __restrict__ Hs,
                          int N, int K, int M, int Kp, int Mp, int transform) {
    __shared__ __align__(16) float As[16][132];
    __shared__ __align__(16) float Bs[16][68];
    int tid = threadIdx.x;        // 256
    int tx = tid & 15, ty = tid >> 4;
    int row0 = blockIdx.y * 128, col0 = blockIdx.x * 64;
    float acc[8][4] = {};

    for (int k0 = 0; k0 < K; k0 += 16) {
        {
            int r  = tid >> 1;          // 0..127
            int c8 = (tid & 1) * 8;     // 0 or 8
            int gr = row0 + r;
#pragma unroll
            for (int i = 0; i < 8; i++) {
                int gk = k0 + c8 + i;
                float v = 0.0f;
                if (gr < N && gk < K) {
                    v = A[(size_t)gr * Kp + gk];
                    if (transform) v = fmaf(fmaxf(v, 0.0f), g_scale[gk], g_shift[gk]);
                }
                As[c8 + i][r] = v;
            }
        }
        {
            int lin = tid * 4;
            int r = lin >> 6;
            int c = lin & 63;
            int gk = k0 + r;
#pragma unroll
            for (int i = 0; i < 4; i++) {
                int gc = col0 + c + i;
                Bs[r][c + i] = (gk < K && gc < M) ? B[(size_t)gk * M + gc] : 0.0f;
            }
        }
        __syncthreads();
#pragma unroll
        for (int kk = 0; kk < 16; kk++) {
            float4 a0 = *(const float4*)&As[kk][ty * 8];
            float4 a1 = *(const float4*)&As[kk][ty * 8 + 4];
            float4 b4 = *(const float4*)&Bs[kk][tx * 4];
            float a[8] = {a0.x, a0.y, a0.z, a0.w, a1.x, a1.y, a1.z, a1.w};
            float bb[4] = {b4.x, b4.y, b4.z, b4.w};
#pragma unroll
            for (int i = 0; i < 8; i++)
#pragma unroll
                for (int j = 0; j < 4; j++)
                    acc[i][j] = fmaf(a[i], bb[j], acc[i][j]);
        }
        __syncthreads();
    }
#pragma unroll
    for (int i = 0; i < 8; i++) {
        int gr = row0 + ty * 8 + i;
        if (gr >= N) continue;
        float dd = g_dinv[gr];
#pragma unroll
        for (int j = 0; j < 4; j++) {
            int gc = col0 + tx * 4 + j;
            if (gc < Mp)
                Hs[(size_t)gr * Mp + gc] = (gc < M) ? acc[i][j] * dd : 0.0f;
        }
    }
}

// ---------------- coalesced CSR pull (+fused BN stats OR fused log_softmax) ----
// out[d] = bias + dinv[d] * (Hs[d] + sum_{s in N(d)} Hs[s])
// mode 1: write G, accumulate BN stats, last block finalizes scale/shift
// mode 2: full row lives in one warp (nch4<=8); log_softmax -> OUT (stride M)
__global__ void k_pull(const float* __restrict__ Hs, const float* __restrict__ bias,
                       float* __restrict__ G, float* __restrict__ OUT,
                       int N, int M, int Mp, int nch4, int ngroups, int mode,
                       const float* __restrict__ gam, const float* __restrict__ bet) {
    __shared__ float sm_s[F_MAX], sm_q[F_MAX];
    int tid = threadIdx.x;
    if (mode == 1) {
        for (int f = tid; f < F_MAX; f += blockDim.x) { sm_s[f] = 0.0f; sm_q[f] = 0.0f; }
        __syncthreads();
    }
    int lane = tid & 31;
    int gw = (blockIdx.x * blockDim.x + tid) >> 5;
    int nw = (gridDim.x * blockDim.x) >> 5;
    int grp = gw % ngroups;
    int c = (grp << 5) + lane;
    bool act = c < nch4;
    int f0 = c << 2;
    float4 b4 = make_float4(0, 0, 0, 0);
    if (act) {
        b4.x = (f0 + 0 < M) ? bias[f0 + 0] : 0.0f;
        b4.y = (f0 + 1 < M) ? bias[f0 + 1] : 0.0f;
        b4.z = (f0 + 2 < M) ? bias[f0 + 2] : 0.0f;
        b4.w = (f0 + 3 < M) ? bias[f0 + 3] : 0.0f;
    }

    if (mode == 2) {
        // all lanes stay in the loop (warp shuffles); loads guarded by act
        for (int d = gw; d < N; d += nw) {
            int beg = g_rowptr[d], end = g_rowptr[d + 1];
            float4 acc = make_float4(0, 0, 0, 0);
            if (act) acc = ((const float4*)(Hs + (size_t)d * Mp))[c];
            int e = beg;
            for (; e + 3 < end; e += 4) {
                int s0 = g_csr[e], s1 = g_csr[e + 1], s2 = g_csr[e + 2], s3 = g_csr[e + 3];
                if (act) {
                    float4 v0 = ((const float4*)(Hs + (size_t)s0 * Mp))[c];
                    float4 v1 = ((const float4*)(Hs + (size_t)s1 * Mp))[c];
                    float4 v2 = ((const float4*)(Hs + (size_t)s2 * Mp))[c];
                    float4 v3 = ((const float4*)(Hs + (size_t)s3 * Mp))[c];
                    acc.x += (v0.x + v1.x) + (v2.x + v3.x);
                    acc.y += (v0.y + v1.y) + (v2.y + v3.y);
                    acc.z += (v0.z + v1.z) + (v2.z + v3.z);
                    acc.w += (v0.w + v1.w) + (v2.w + v3.w);
                }
            }
            for (; e < end; e++) {
                int s0 = g_csr[e];
                if (act) {
                    float4 v0 = ((const float4*)(Hs + (size_t)s0 * Mp))[c];
                    acc.x += v0.x; acc.y += v0.y; acc.z += v0.z; acc.w += v0.w;
                }
            }
            float dd = g_dinv[d];
            float4 o;
            o.x = fmaf(dd, acc.x, b4.x);
            o.y = fmaf(dd, acc.y, b4.y);
            o.z = fmaf(dd, acc.z, b4.z);
            o.w = fmaf(dd, acc.w, b4.w);
            bool vx = act && (f0 + 0 < M), vy = act && (f0 + 1 < M);
            bool vz = act && (f0 + 2 < M), vw = act && (f0 + 3 < M);
            float m = fmaxf(fmaxf(vx ? o.x : -1e30f, vy ? o.y : -1e30f),
                            fmaxf(vz ? o.z : -1e30f, vw ? o.w : -1e30f));
#pragma unroll
            for (int off = 16; off; off >>= 1)
                m = fmaxf(m, __shfl_xor_sync(0xFFFFFFFFu, m, off));
            float s = (vx ? expf(o.x - m) : 0.0f) + (vy ? expf(o.y - m) : 0.0f)
                    + (vz ? expf(o.z - m) : 0.0f) + (vw ? expf(o.w - m) : 0.0f);
#pragma unroll
            for (int off = 16; off; off >>= 1)
                s += __shfl_xor_sync(0xFFFFFFFFu, s, off);
            float lse = m + logf(s);
            float* orow = OUT + (size_t)d * M;
            if (vx) orow[f0 + 0] = o.x - lse;
            if (vy) orow[f0 + 1] = o.y - lse;
            if (vz) orow[f0 + 2] = o.z - lse;
            if (vw) orow[f0 + 3] = o.w - lse;
        }
        return;
    }

    float4 ls = make_float4(0, 0, 0, 0), lq = make_float4(0, 0, 0, 0);
    for (int d = gw / ngroups; d < N; d += nw / ngroups) {
        if (!act) continue;
        int beg = g_rowptr[d], end = g_rowptr[d + 1];
        float4 acc = ((const float4*)(Hs + (size_t)d * Mp))[c];
        int e = beg;
        for (; e + 3 < end; e += 4) {
            int s0 = g_csr[e], s1 = g_csr[e + 1], s2 = g_csr[e + 2], s3 = g_csr[e + 3];
            float4 v0 = ((const float4*)(Hs + (size_t)s0 * Mp))[c];
            float4 v1 = ((const float4*)(Hs + (size_t)s1 * Mp))[c];
            float4 v2 = ((const float4*)(Hs + (size_t)s2 * Mp))[c];
            float4 v3 = ((const float4*)(Hs + (size_t)s3 * Mp))[c];
            acc.x += (v0.x + v1.x) + (v2.x + v3.x);
            acc.y += (v0.y + v1.y) + (v2.y + v3.y);
            acc.z += (v0.z + v1.z) + (v2.z + v3.z);
            acc.w += (v0.w + v1.w) + (v2.w + v3.w);
        }
        for (; e < end; e++) {
            int s0 = g_csr[e];
            float4 v0 = ((const float4*)(Hs + (size_t)s0 * Mp))[c];
            acc.x += v0.x; acc.y += v0.y; acc.z += v0.z; acc.w += v0.w;
        }
        float dd = g_dinv[d];
        float4 o;
        o.x = fmaf(dd, acc.x, b4.x);
        o.y = fmaf(dd, acc.y, b4.y);
        o.z = fmaf(dd, acc.z, b4.z);
        o.w = fmaf(dd, acc.w, b4.w);
        ((float4*)(G + (size_t)d * Mp))[c] = o;
        float rx = fmaxf(o.x, 0.0f), ry = fmaxf(o.y, 0.0f);
        float rz = fmaxf(o.z, 0.0f), rw = fmaxf(o.w, 0.0f);
        ls.x += rx; ls.y += ry; ls.z += rz; ls.w += rw;
        lq.x += rx * rx; lq.y += ry * ry; lq.z += rz * rz; lq.w += rw * rw;
    }

    if (act) {
        atomicAdd(&sm_s[f0 + 0], ls.x); atomicAdd(&sm_q[f0 + 0], lq.x);
        atomicAdd(&sm_s[f0 + 1], ls.y); atomicAdd(&sm_q[f0 + 1], lq.y);
        atomicAdd(&sm_s[f0 + 2], ls.z); atomicAdd(&sm_q[f0 + 2], lq.z);
        atomicAdd(&sm_s[f0 + 3], ls.w); atomicAdd(&sm_q[f0 + 3], lq.w);
    }
    __syncthreads();
    for (int f = tid; f < M; f += blockDim.x) {
        atomicAdd(&g_sum[f], sm_s[f]);
        atomicAdd(&g_sumsq[f], sm_q[f]);
    }
    __threadfence();
    __syncthreads();
    __shared__ int is_last;
    if (tid == 0) {
        unsigned t = atomicAdd(&g_ticket, 1u);
        is_last = (t == gridDim.x - 1);
    }
    __syncthreads();
    if (is_last) {
        for (int f = tid; f < M; f += blockDim.x) {
            float mu = g_sum[f] / (float)N;
            float var = g_sumsq[f] / (float)N - mu * mu;
            float istd = rsqrtf(fmaxf(var, 0.0f) + 1e-5f);
            float sc = istd * gam[f];
            g_scale[f] = sc;
            g_shift[f] = bet[f] - mu * sc;
            g_sum[f] = 0.0f;
            g_sumsq[f] = 0.0f;
        }
        if (tid == 0) g_ticket = 0;
    }
}

// ---------------- orchestration ----------------
extern "C" void kernel_launch(void* const* d_in, const int* in_sizes, int n_in,
                              void* d_out, int out_size) {
    const float* x = (const float*)d_in[0];
    const void* ei = d_in[1];
    const float *W[5], *b[5], *gam[4], *bet[4];
    for (int i = 0; i < 5; i++) {
        W[i] = (const float*)d_in[2 + 2 * i];
        b[i] = (const float*)d_in[3 + 2 * i];
    }
    for (int i = 0; i < 4; i++) {
        gam[i] = (const float*)d_in[12 + 2 * i];
        bet[i] = (const float*)d_in[13 + 2 * i];
    }
    int dims[6];
    for (int i = 0; i < 5; i++) dims[i + 1] = in_sizes[3 + 2 * i];
    dims[0] = in_sizes[2] / dims[1];
    int N = in_sizes[0] / dims[0];
    int E = in_sizes[1] / 2;

    float *bufH, *bufG[2];
    cudaGetSymbolAddress((void**)&bufH, g_bufH);
    cudaGetSymbolAddress((void**)&bufG[0], g_bufG0);
    cudaGetSymbolAddress((void**)&bufG[1], g_bufG1);

    k_init<<<(N + 255) / 256, 256>>>((const int*)ei, N);
    k_count<<<256, 256>>>(ei, E);
    k_scan<<<1, 1024>>>(N);
    k_scatter<<<256, 256>>>(ei, E);

    const float* in = x;
    int Kp = dims[0];
    int transform = 0;
    for (int l = 0; l < 5; l++) {
        int K = dims[l], M = dims[l + 1];
        int Mp = (M + 3) & ~3;
        float* G = bufG[l & 1];

        int colT = (Mp + 63) / 64;
        int rows128 = (N + 127) / 128;
        if (rows128 * colT >= 148) {
            dim3 grid(colT, rows128);
            k_gemm128<<<grid, 256>>>(in, W[l], bufH, N, K, M, Kp, Mp, transform);
        } else {
            dim3 grid(colT, (N + 63) / 64);
            k_gemm64<<<grid, 256>>>(in, W[l], bufH, N, K, M, Kp, Mp, transform);
        }

        int nch4 = Mp >> 2;
        int ngroups = (nch4 + 31) >> 5;
        int mode = (l < 4) ? 1 : 2;
        k_pull<<<1184, 256>>>(bufH, b[l], G, (float*)d_out, N, M, Mp, nch4,
                              (mode == 2) ? 1 : ngroups, mode,
                              (l < 4) ? gam[l] : b[l], (l < 4) ? bet[l] : b[l]);

        if (l < 4) {
            in = G;
            Kp = Mp;
            transform = 1;
        }
    }
}